// round 4
// baseline (speedup 1.0000x reference)
#include <cuda_runtime.h>
#include <math.h>
#include <stdint.h>

// ============================================================================
// EcosystemTransformer — tf32 mma, 3-stage cp.async GEMMs, pipelined flash attn
//   B=4, N=1024, D=512, H=8, L=6, DFF=2048, DH=64
// ============================================================================

namespace {
constexpr int Bv   = 4;
constexpr int Nv   = 1024;
constexpr int Dv   = 512;
constexpr int Lv   = 6;
constexpr int DFFv = 2048;
constexpr int DHv  = 64;
constexpr int ROWS = Bv * Nv;           // 4096
constexpr float NEGINF = -1000000000.0f;
constexpr float R2 = 100.0f;

constexpr int BM  = 128;
constexpr int BK  = 16;
constexpr int AST = 20;
}

// Scratch buffers
__device__ __align__(16) float g_x [ROWS * Dv];
__device__ __align__(16) float g_h [ROWS * Dv];
__device__ __align__(16) float g_q [ROWS * Dv];
__device__ __align__(16) float g_k [ROWS * Dv];
__device__ __align__(16) float g_v [ROWS * Dv];
__device__ __align__(16) float g_o [ROWS * Dv];
__device__ __align__(16) float g_ff[ROWS * DFFv];
__device__ __align__(16) float4 g_kattr[ROWS];        // (x, y, deadbias, isagent)

// rna-rounded tf32 weight copies
__device__ __align__(16) float g_Wq[Lv * Dv * Dv];
__device__ __align__(16) float g_Wk[Lv * Dv * Dv];
__device__ __align__(16) float g_Wv[Lv * Dv * Dv];
__device__ __align__(16) float g_Wo[Lv * Dv * Dv];
__device__ __align__(16) float g_W1[Lv * Dv * DFFv];
__device__ __align__(16) float g_W2[Lv * DFFv * Dv];

__device__ __forceinline__ float* selbuf(int s) {
    switch (s) {
        case 0: return g_h;
        case 1: return g_o;
        case 2: return g_ff;
        case 3: return g_q;
        case 4: return g_k;
        case 5: return g_v;
        default: return g_x;
    }
}
__device__ __forceinline__ float* selw(int s) {
    switch (s) {
        case 0: return g_Wq;
        case 1: return g_Wk;
        case 2: return g_Wv;
        case 3: return g_Wo;
        case 4: return g_W1;
        default: return g_W2;
    }
}

// ---------------------------------------------------------------------------
// helpers
// ---------------------------------------------------------------------------
__device__ __forceinline__ float to_tf32(float x) {
    uint32_t u;
    asm("cvt.rna.tf32.f32 %0, %1;" : "=r"(u) : "f"(x));
    return __uint_as_float(u);
}
__device__ __forceinline__ float4 to_tf32_4(float4 v) {
    return make_float4(to_tf32(v.x), to_tf32(v.y), to_tf32(v.z), to_tf32(v.w));
}

__device__ __forceinline__ void cp_async16(void* smem_dst, const void* gmem_src) {
    uint32_t s = (uint32_t)__cvta_generic_to_shared(smem_dst);
    asm volatile("cp.async.ca.shared.global [%0], [%1], 16;\n"
                 :: "r"(s), "l"(__cvta_generic_to_global(gmem_src)) : "memory");
}
__device__ __forceinline__ void cp_commit() {
    asm volatile("cp.async.commit_group;\n" ::: "memory");
}
template <int N>
__device__ __forceinline__ void cp_wait() {
    asm volatile("cp.async.wait_group %0;\n" :: "n"(N) : "memory");
}

__device__ __forceinline__ void mma_tf32(float c[4], const uint32_t a[4],
                                         uint32_t b0, uint32_t b1) {
    asm volatile(
        "mma.sync.aligned.m16n8k8.row.col.f32.tf32.tf32.f32 "
        "{%0,%1,%2,%3}, {%4,%5,%6,%7}, {%8,%9}, {%0,%1,%2,%3};"
        : "+f"(c[0]), "+f"(c[1]), "+f"(c[2]), "+f"(c[3])
        : "r"(a[0]), "r"(a[1]), "r"(a[2]), "r"(a[3]), "r"(b0), "r"(b1));
}

template <int NT, int BST>
__device__ __forceinline__ void compute_bk(const float* __restrict__ As,
                                           const float* __restrict__ Bs,
                                           float acc[2][NT][4],
                                           int lane, int warpM, int warpN) {
    const int gid = lane >> 2, tig = lane & 3;
    #pragma unroll
    for (int kk = 0; kk < 16; kk += 8) {
        uint32_t a[2][4];
        #pragma unroll
        for (int mt = 0; mt < 2; mt++) {
            const int m = warpM + mt * 16;
            a[mt][0] = __float_as_uint(As[(m + gid)     * AST + kk + tig]);
            a[mt][1] = __float_as_uint(As[(m + gid + 8) * AST + kk + tig]);
            a[mt][2] = __float_as_uint(As[(m + gid)     * AST + kk + tig + 4]);
            a[mt][3] = __float_as_uint(As[(m + gid + 8) * AST + kk + tig + 4]);
        }
        #pragma unroll
        for (int nt = 0; nt < NT; nt++) {
            const int n = warpN + nt * 8 + gid;
            uint32_t b0 = __float_as_uint(Bs[(kk + tig)     * BST + n]);
            uint32_t b1 = __float_as_uint(Bs[(kk + tig + 4) * BST + n]);
            mma_tf32(acc[0][nt], a[0], b0, b1);
            mma_tf32(acc[1][nt], a[1], b0, b1);
        }
    }
}

// 64-deep K slab, single 16-row m-tile: acc[NT][4]
template <int NT>
__device__ __forceinline__ void mma_slab64(const float* __restrict__ As, int ast,
                                           const float* __restrict__ Bs, int bst,
                                           float acc[NT][4], int lane, int rowBase) {
    const int gid = lane >> 2, tig = lane & 3;
    #pragma unroll
    for (int kk = 0; kk < 64; kk += 8) {
        uint32_t a[4];
        a[0] = __float_as_uint(As[(rowBase + gid)     * ast + kk + tig]);
        a[1] = __float_as_uint(As[(rowBase + gid + 8) * ast + kk + tig]);
        a[2] = __float_as_uint(As[(rowBase + gid)     * ast + kk + tig + 4]);
        a[3] = __float_as_uint(As[(rowBase + gid + 8) * ast + kk + tig + 4]);
        #pragma unroll
        for (int nt = 0; nt < NT; nt++) {
            uint32_t b0 = __float_as_uint(Bs[(kk + tig)     * bst + nt * 8 + gid]);
            uint32_t b1 = __float_as_uint(Bs[(kk + tig + 4) * bst + nt * 8 + gid]);
            mma_tf32(acc[nt], a, b0, b1);
        }
    }
}

// ----------------------------------------------------------------------------
// small utility kernels
// ----------------------------------------------------------------------------
__global__ void __launch_bounds__(256)
copy_tokens(const float4* __restrict__ tokens) {
    int i = blockIdx.x * 256 + threadIdx.x;
    ((float4*)g_x)[i] = tokens[i];
}

__global__ void __launch_bounds__(256)
round_w(int wSel, const float4* __restrict__ src, int n4) {
    int i = blockIdx.x * 256 + threadIdx.x;
    if (i < n4) ((float4*)selw(wSel))[i] = to_tf32_4(src[i]);
}

__global__ void __launch_bounds__(256)
kattr_build(const float* __restrict__ xy, const int* __restrict__ alive,
            const int* __restrict__ species) {
    int i = blockIdx.x * 256 + threadIdx.x;   // < ROWS
    g_kattr[i] = make_float4(xy[2 * i], xy[2 * i + 1],
                             alive[i] ? 0.f : NEGINF,
                             (species[i] < 2) ? 1.f : 0.f);
}

// ----------------------------------------------------------------------------
// LayerNorm: warp per row, float4 vectorized. roundOut -> rna-tf32 store.
// ----------------------------------------------------------------------------
__global__ void __launch_bounds__(256)
ln_kernel(int inSel, int outSel, float* __restrict__ outPtr,
          const float* __restrict__ g, const float* __restrict__ be, int roundOut) {
    const float* in = selbuf(inSel);
    float* out = (outSel == 0) ? g_h : outPtr;
    const int row = blockIdx.x * 8 + (threadIdx.x >> 5);
    const int lane = threadIdx.x & 31;
    const float4* xr = (const float4*)(in + (size_t)row * Dv);

    float4 v[4];
    #pragma unroll
    for (int i = 0; i < 4; i++) v[i] = xr[lane + 32 * i];

    float s = 0.f;
    #pragma unroll
    for (int i = 0; i < 4; i++) s += v[i].x + v[i].y + v[i].z + v[i].w;
    #pragma unroll
    for (int o = 16; o; o >>= 1) s += __shfl_xor_sync(0xffffffffu, s, o);
    const float mean = s * (1.0f / Dv);

    float q = 0.f;
    #pragma unroll
    for (int i = 0; i < 4; i++) {
        float a = v[i].x - mean, b = v[i].y - mean;
        float c = v[i].z - mean, d = v[i].w - mean;
        q += a * a + b * b + c * c + d * d;
    }
    #pragma unroll
    for (int o = 16; o; o >>= 1) q += __shfl_xor_sync(0xffffffffu, q, o);
    const float rs = rsqrtf(q * (1.0f / Dv) + 1e-5f);

    const float4* g4  = (const float4*)g;
    const float4* be4 = (const float4*)be;
    float4* o4 = (float4*)(out + (size_t)row * Dv);
    #pragma unroll
    for (int i = 0; i < 4; i++) {
        float4 gg = g4[lane + 32 * i], bb = be4[lane + 32 * i];
        float4 r;
        r.x = (v[i].x - mean) * rs * gg.x + bb.x;
        r.y = (v[i].y - mean) * rs * gg.y + bb.y;
        r.z = (v[i].z - mean) * rs * gg.z + bb.z;
        r.w = (v[i].w - mean) * rs * gg.w + bb.w;
        if (roundOut) r = to_tf32_4(r);
        o4[lane + 32 * i] = r;
    }
}

// ----------------------------------------------------------------------------
// 3-stage cp.async tensor-core NN GEMM, single sync per BK slab.
//   EPI 0: C = rna(acc);  EPI 1: C += acc + bias;  EPI 2: C = rna(gelu(acc+bias))
// ----------------------------------------------------------------------------
template <int EPI, int BN>
__global__ void __launch_bounds__(256, 2)
gemm3(int aSel, int wSel, size_t wOff, int cSelBase, int Nn, int K,
      const float* __restrict__ bias) {
    constexpr int BST = BN + 8;
    constexpr int NT  = BN / 16;

    extern __shared__ float smg[];
    float* As = smg;                       // 3 * BM*AST
    float* Bs = smg + 3 * BM * AST;        // 3 * BK*BST

    const int z = blockIdx.z;
    const float* A = selbuf(aSel);
    const float* W = selw(wSel + z) + wOff;
    float* C = selbuf(cSelBase + z);

    const int tid  = threadIdx.x;
    const int lane = tid & 31;
    const int wid  = tid >> 5;
    const int warpM = (wid & 3) * 32;
    const int warpN = (wid >> 2) * (BN / 2);
    const int m0 = blockIdx.y * BM;
    const int n0 = blockIdx.x * BN;

    const int arow  = tid >> 2, ac4 = (tid & 3) * 4;
    const int arow2 = arow + 64;

    const float* Ag = A + (size_t)m0 * K;
    const float* Bg = W + n0;

    auto load_stage = [&](int buf, int k0) {
        float* Ab = As + buf * (BM * AST);
        float* Bb = Bs + buf * (BK * BST);
        cp_async16(&Ab[arow  * AST + ac4], Ag + (size_t)arow  * K + k0 + ac4);
        cp_async16(&Ab[arow2 * AST + ac4], Ag + (size_t)arow2 * K + k0 + ac4);
        if (BN == 128) {
            int brow = tid >> 5, bc = (tid & 31) * 4;
            cp_async16(&Bb[brow * BST + bc],       Bg + (size_t)(k0 + brow)     * Nn + bc);
            cp_async16(&Bb[(brow + 8) * BST + bc], Bg + (size_t)(k0 + brow + 8) * Nn + bc);
        } else {
            int brow = tid >> 4, bc = (tid & 15) * 4;
            cp_async16(&Bb[brow * BST + bc],       Bg + (size_t)(k0 + brow)     * Nn + bc);
        }
        cp_commit();
    };

    float acc[2][NT][4] = {};

    load_stage(0, 0);
    load_stage(1, BK);
    const int T = K / BK;
    for (int i = 0; i < T; i++) {
        cp_wait<1>();
        __syncthreads();
        if (i + 2 < T) load_stage((i + 2) % 3, (i + 2) * BK);
        else           cp_commit();        // keep group numbering
        const int buf = i % 3;
        compute_bk<NT, BST>(As + buf * (BM * AST), Bs + buf * (BK * BST),
                            acc, lane, warpM, warpN);
    }

    const int gid = lane >> 2, tig = lane & 3;
    #pragma unroll
    for (int mt = 0; mt < 2; mt++) {
        #pragma unroll
        for (int half = 0; half < 2; half++) {
            const int row = m0 + warpM + mt * 16 + gid + half * 8;
            #pragma unroll
            for (int nt = 0; nt < NT; nt++) {
                const int col = n0 + warpN + nt * 8 + 2 * tig;
                float v0 = acc[mt][nt][half * 2 + 0];
                float v1 = acc[mt][nt][half * 2 + 1];
                float* Cp = C + (size_t)row * Nn + col;
                if (EPI == 0) {
                    Cp[0] = to_tf32(v0); Cp[1] = to_tf32(v1);
                } else if (EPI == 1) {
                    Cp[0] = Cp[0] + (v0 + bias[col]);
                    Cp[1] = Cp[1] + (v1 + bias[col + 1]);
                } else {
                    float u0 = v0 + bias[col];
                    float u1 = v1 + bias[col + 1];
                    Cp[0] = to_tf32(0.5f * u0 * (1.0f + erff(u0 * 0.70710678118654752f)));
                    Cp[1] = to_tf32(0.5f * u1 * (1.0f + erff(u1 * 0.70710678118654752f)));
                }
            }
        }
    }
}

// ----------------------------------------------------------------------------
// Pipelined flash attention. 128 q-rows per block, 8 warps x 16 rows.
// Double-buffered V (cp.async) + K (register prefetch), 1 syncthreads/chunk.
// ----------------------------------------------------------------------------
__global__ void __launch_bounds__(256)
flash_attn() {
    constexpr int QT = 128, JT = 64;
    constexpr int QST = 68, PST = 68, KST = 72, VST = 72;
    constexpr int KVB = JT * KST;   // 4608 floats per buffer

    extern __shared__ float sm[];
    float*  Qs = sm;                       // 128*68 = 8704
    float*  Ps = Qs + QT * QST;            // 8704
    float*  Ks = Ps + QT * PST;            // 2*4608
    float*  Vs = Ks + 2 * KVB;             // 2*4608
    float4* Ka = (float4*)(Vs + 2 * KVB);  // 2*64 float4

    const int tid = threadIdx.x, lane = tid & 31, wid = tid >> 5;
    const int gid = lane >> 2, tig = lane & 3;
    const int m0 = blockIdx.x * QT;
    const int z = blockIdx.y, bb = z >> 3, hh = z & 7;

    const float* __restrict__ Qg = g_q + (size_t)bb * Nv * Dv + hh * DHv;
    const float* __restrict__ Kg = g_k + (size_t)bb * Nv * Dv + hh * DHv;
    const float* __restrict__ Vg = g_v + (size_t)bb * Nv * Dv + hh * DHv;
    float*       __restrict__ Og = g_o + (size_t)bb * Nv * Dv + hh * DHv;
    const float4* __restrict__ kat = g_kattr + bb * Nv;

    // group 0: Q tile + V chunk 0 + attrs chunk 0
    #pragma unroll
    for (int s = 0; s < 8; s++) {
        int slot = tid + s * 256;
        int qr = slot >> 4, q4 = (slot & 15) * 4;
        cp_async16(&Qs[qr * QST + q4], Qg + (size_t)(m0 + qr) * Dv + q4);
    }
    #pragma unroll
    for (int s = 0; s < 4; s++) {
        int slot = tid + s * 256;
        int jl = slot >> 4, d4 = (slot & 15) * 4;
        cp_async16(&Vs[jl * VST + d4], Vg + (size_t)jl * Dv + d4);
    }
    if (tid < JT) cp_async16(&Ka[tid], kat + tid);
    cp_commit();

    // K chunk 0 -> registers (lane-consecutive j: conflict-free STS later)
    float4 kreg[4];
    #pragma unroll
    for (int s = 0; s < 4; s++) {
        int slot = tid + s * 256;
        int jl = slot & 63, d4 = (slot >> 6) * 4;
        kreg[s] = *(const float4*)(Kg + (size_t)jl * Dv + d4);
    }

    // per-thread query attrs
    const int r0 = wid * 16 + gid, r1 = r0 + 8;
    const float4 qa0 = kat[m0 + r0];
    const float4 qa1 = kat[m0 + r1];

    float accO[8][4] = {};
    float mrow0 = -INFINITY, mrow1 = -INFINITY;
    float lrow0 = 0.f, lrow1 = 0.f;

    for (int i = 0; i < Nv / JT; i++) {
        const int buf = i & 1;
        float* Kb = Ks + buf * KVB;
        float* Vb = Vs + buf * KVB;
        const float4* Kab = Ka + buf * 64;

        // transpose-store K(i): conflict-free (lane-consecutive jl)
        #pragma unroll
        for (int s = 0; s < 4; s++) {
            int slot = tid + s * 256;
            int jl = slot & 63, d = (slot >> 6) * 4;
            Kb[(d + 0) * KST + jl] = kreg[s].x;
            Kb[(d + 1) * KST + jl] = kreg[s].y;
            Kb[(d + 2) * KST + jl] = kreg[s].z;
            Kb[(d + 3) * KST + jl] = kreg[s].w;
        }
        cp_wait<0>();          // V(i) + attrs(i) (+Q on i=0) complete
        __syncthreads();       // K(i) STS visible to all

        if (i + 1 < Nv / JT) {
            const int j0n = (i + 1) * JT;
            #pragma unroll
            for (int s = 0; s < 4; s++) {
                int slot = tid + s * 256;
                int jl = slot >> 4, d4 = (slot & 15) * 4;
                cp_async16(&Vs[(buf ^ 1) * KVB + jl * VST + d4],
                           Vg + (size_t)(j0n + jl) * Dv + d4);
            }
            if (tid < JT) cp_async16(&Ka[(buf ^ 1) * 64 + tid], kat + j0n + tid);
            cp_commit();
            #pragma unroll
            for (int s = 0; s < 4; s++) {
                int slot = tid + s * 256;
                int jl = slot & 63, d4 = (slot >> 6) * 4;
                kreg[s] = *(const float4*)(Kg + (size_t)(j0n + jl) * Dv + d4);
            }
        }

        // S = Q K^T for this warp's 16 rows
        float accS[8][4] = {};
        mma_slab64<8>(Qs, QST, Kb, KST, accS, lane, wid * 16);

        // bias + chunk max
        float mc0 = -INFINITY, mc1 = -INFINITY;
        #pragma unroll
        for (int nt = 0; nt < 8; nt++) {
            #pragma unroll
            for (int c = 0; c < 2; c++) {
                int jl = nt * 8 + 2 * tig + c;
                float4 ka = Kab[jl];
                float b0 = ka.z, b1 = ka.z;
                float dx0 = qa0.x - ka.x, dy0 = qa0.y - ka.y;
                float dx1 = qa1.x - ka.x, dy1 = qa1.y - ka.y;
                if (dx0 * dx0 + dy0 * dy0 > R2) b0 += NEGINF;
                if (qa0.w != ka.w)              b0 += NEGINF;
                if (dx1 * dx1 + dy1 * dy1 > R2) b1 += NEGINF;
                if (qa1.w != ka.w)              b1 += NEGINF;
                float s0 = accS[nt][c]     * 0.125f + b0;
                float s1 = accS[nt][c + 2] * 0.125f + b1;
                accS[nt][c]     = s0; mc0 = fmaxf(mc0, s0);
                accS[nt][c + 2] = s1; mc1 = fmaxf(mc1, s1);
            }
        }
        mc0 = fmaxf(mc0, __shfl_xor_sync(0xffffffffu, mc0, 1));
        mc0 = fmaxf(mc0, __shfl_xor_sync(0xffffffffu, mc0, 2));
        mc1 = fmaxf(mc1, __shfl_xor_sync(0xffffffffu, mc1, 1));
        mc1 = fmaxf(mc1, __shfl_xor_sync(0xffffffffu, mc1, 2));

        float mn0 = fmaxf(mrow0, mc0), mn1 = fmaxf(mrow1, mc1);
        float sc0 = __expf(mrow0 - mn0), sc1 = __expf(mrow1 - mn1);

        float sum0 = 0.f, sum1 = 0.f;
        #pragma unroll
        for (int nt = 0; nt < 8; nt++) {
            #pragma unroll
            for (int c = 0; c < 2; c++) {
                int jl = nt * 8 + 2 * tig + c;
                float p0 = __expf(accS[nt][c]     - mn0);
                float p1 = __expf(accS[nt][c + 2] - mn1);
                sum0 += p0; sum1 += p1;
                Ps[r0 * PST + jl] = p0;
                Ps[r1 * PST + jl] = p1;
            }
        }
        sum0 += __shfl_xor_sync(0xffffffffu, sum0, 1);
        sum0 += __shfl_xor_sync(0xffffffffu, sum0, 2);
        sum1 += __shfl_xor_sync(0xffffffffu, sum1, 1);
        sum1 += __shfl_xor_sync(0xffffffffu, sum1, 2);

        lrow0 = lrow0 * sc0 + sum0;
        lrow1 = lrow1 * sc1 + sum1;
        mrow0 = mn0; mrow1 = mn1;

        #pragma unroll
        for (int nt = 0; nt < 8; nt++) {
            accO[nt][0] *= sc0; accO[nt][1] *= sc0;
            accO[nt][2] *= sc1; accO[nt][3] *= sc1;
        }

        __syncwarp();
        mma_slab64<8>(Ps, PST, Vb, VST, accO, lane, wid * 16);
    }

    // epilogue: normalize, rna-round (O feeds Wo GEMM A-operand), store
    float il0 = 1.f / lrow0, il1 = 1.f / lrow1;
    #pragma unroll
    for (int nt = 0; nt < 8; nt++) {
        int col = nt * 8 + 2 * tig;
        float* o0 = Og + (size_t)(m0 + r0) * Dv + col;
        float* o1 = Og + (size_t)(m0 + r1) * Dv + col;
        o0[0] = to_tf32(accO[nt][0] * il0); o0[1] = to_tf32(accO[nt][1] * il0);
        o1[0] = to_tf32(accO[nt][2] * il1); o1[1] = to_tf32(accO[nt][3] * il1);
    }
}

// ============================================================================
// Launch sequence
// ============================================================================
extern "C" void kernel_launch(void* const* d_in, const int* in_sizes, int n_in,
                              void* d_out, int out_size) {
    const float* tokens = (const float*)d_in[0];
    const float* xy     = (const float*)d_in[1];
    const float* Wq     = (const float*)d_in[2];
    const float* Wk     = (const float*)d_in[3];
    const float* Wv     = (const float*)d_in[4];
    const float* Wo     = (const float*)d_in[5];
    const float* bo     = (const float*)d_in[6];
    const float* W1     = (const float*)d_in[7];
    const float* b1     = (const float*)d_in[8];
    const float* W2     = (const float*)d_in[9];
    const float* b2     = (const float*)d_in[10];
    const float* g1     = (const float*)d_in[11];
    const float* be1    = (const float*)d_in[12];
    const float* g2     = (const float*)d_in[13];
    const float* be2    = (const float*)d_in[14];
    const float* gf     = (const float*)d_in[15];
    const float* bf     = (const float*)d_in[16];
    const int*   alive  = (const int*)d_in[17];
    const int*   species= (const int*)d_in[18];
    float* out = (float*)d_out;

    constexpr int GS128 = 3 * (BM * AST + BK * 136) * 4;   // 56832
    constexpr int GS64  = 3 * (BM * AST + BK * 72)  * 4;   // 44544
    constexpr int FLASH_SMEM = (128 * 68 * 2 + 64 * 72 * 2 * 2) * 4 + 2 * 64 * 16; // 145408

    cudaFuncSetAttribute(gemm3<0,128>, cudaFuncAttributeMaxDynamicSharedMemorySize, GS128);
    cudaFuncSetAttribute(gemm3<2,128>, cudaFuncAttributeMaxDynamicSharedMemorySize, GS128);
    cudaFuncSetAttribute(gemm3<1,64>,  cudaFuncAttributeMaxDynamicSharedMemorySize, GS64);
    cudaFuncSetAttribute(flash_attn,   cudaFuncAttributeMaxDynamicSharedMemorySize, FLASH_SMEM);

    // rna-round weights once per launch
    {
        int n4a = Lv * Dv * Dv / 4;        // 393216
        int n4b = Lv * Dv * DFFv / 4;      // 1572864
        round_w<<<(n4a + 255) / 256, 256>>>(0, (const float4*)Wq, n4a);
        round_w<<<(n4a + 255) / 256, 256>>>(1, (const float4*)Wk, n4a);
        round_w<<<(n4a + 255) / 256, 256>>>(2, (const float4*)Wv, n4a);
        round_w<<<(n4a + 255) / 256, 256>>>(3, (const float4*)Wo, n4a);
        round_w<<<(n4b + 255) / 256, 256>>>(4, (const float4*)W1, n4b);
        round_w<<<(n4b + 255) / 256, 256>>>(5, (const float4*)W2, n4b);
    }
    kattr_build<<<ROWS / 256, 256>>>(xy, alive, species);
    copy_tokens<<<(ROWS * Dv / 4) / 256, 256>>>((const float4*)tokens);

    for (int l = 0; l < Lv; l++) {
        const size_t oD = (size_t)l * Dv * Dv;
        const size_t oF = (size_t)l * Dv * DFFv;
        // ln1: x -> h (rounded)
        ln_kernel<<<ROWS / 8, 256>>>(6, 0, nullptr, g1 + l * Dv, be1 + l * Dv, 1);
        // fused QKV
        gemm3<0,128><<<dim3(Dv / 128, ROWS / 128, 3), 256, GS128>>>(
            0, 0, oD, 3, Dv, Dv, nullptr);
        // flash attention -> o (rounded)
        flash_attn<<<dim3(Nv / 128, Bv * 8), 256, FLASH_SMEM>>>();
        // x += o Wo + bo
        gemm3<1,64><<<dim3(Dv / 64, ROWS / 128, 1), 256, GS64>>>(
            1, 3, oD, 6, Dv, Dv, bo + l * Dv);
        // ln2: x -> h (rounded)
        ln_kernel<<<ROWS / 8, 256>>>(6, 0, nullptr, g2 + l * Dv, be2 + l * Dv, 1);
        // ff = gelu(h W1 + b1) (rounded)
        gemm3<2,128><<<dim3(DFFv / 128, ROWS / 128, 1), 256, GS128>>>(
            0, 4, oF, 2, DFFv, Dv, b1 + l * DFFv);
        // x += ff W2 + b2
        gemm3<1,64><<<dim3(Dv / 64, ROWS / 128, 1), 256, GS64>>>(
            2, 5, oF, 6, Dv, DFFv, b2 + l * Dv);
    }

    // final layernorm -> out (full fp32)
    ln_kernel<<<ROWS / 8, 256>>>(6, 1, out, gf, bf, 0);
}

// round 6
// speedup vs baseline: 1.1048x; 1.1048x over previous
#include <cuda_runtime.h>
#include <math.h>
#include <stdint.h>

// ============================================================================
// EcosystemTransformer — tf32 mma, 3-stage cp.async GEMMs,
//   flash attention v3: register-resident P (quad-shuffle frag conversion),
//   2 CTAs/SM occupancy.
//   B=4, N=1024, D=512, H=8, L=6, DFF=2048, DH=64
// ============================================================================

namespace {
constexpr int Bv   = 4;
constexpr int Nv   = 1024;
constexpr int Dv   = 512;
constexpr int Lv   = 6;
constexpr int DFFv = 2048;
constexpr int DHv  = 64;
constexpr int ROWS = Bv * Nv;           // 4096
constexpr float NEGINF = -1000000000.0f;
constexpr float R2 = 100.0f;

constexpr int BM  = 128;
constexpr int BK  = 16;
constexpr int AST = 20;
}

// Scratch buffers
__device__ __align__(16) float g_x [ROWS * Dv];
__device__ __align__(16) float g_h [ROWS * Dv];
__device__ __align__(16) float g_q [ROWS * Dv];
__device__ __align__(16) float g_k [ROWS * Dv];
__device__ __align__(16) float g_v [ROWS * Dv];
__device__ __align__(16) float g_o [ROWS * Dv];
__device__ __align__(16) float g_ff[ROWS * DFFv];
__device__ __align__(16) float4 g_kattr[ROWS];        // (x, y, deadbias, isagent)

// rna-rounded tf32 weight copies
__device__ __align__(16) float g_Wq[Lv * Dv * Dv];
__device__ __align__(16) float g_Wk[Lv * Dv * Dv];
__device__ __align__(16) float g_Wv[Lv * Dv * Dv];
__device__ __align__(16) float g_Wo[Lv * Dv * Dv];
__device__ __align__(16) float g_W1[Lv * Dv * DFFv];
__device__ __align__(16) float g_W2[Lv * DFFv * Dv];

__device__ __forceinline__ float* selbuf(int s) {
    switch (s) {
        case 0: return g_h;
        case 1: return g_o;
        case 2: return g_ff;
        case 3: return g_q;
        case 4: return g_k;
        case 5: return g_v;
        default: return g_x;
    }
}
__device__ __forceinline__ float* selw(int s) {
    switch (s) {
        case 0: return g_Wq;
        case 1: return g_Wk;
        case 2: return g_Wv;
        case 3: return g_Wo;
        case 4: return g_W1;
        default: return g_W2;
    }
}

// ---------------------------------------------------------------------------
// helpers
// ---------------------------------------------------------------------------
__device__ __forceinline__ float to_tf32(float x) {
    uint32_t u;
    asm("cvt.rna.tf32.f32 %0, %1;" : "=r"(u) : "f"(x));
    return __uint_as_float(u);
}
__device__ __forceinline__ float4 to_tf32_4(float4 v) {
    return make_float4(to_tf32(v.x), to_tf32(v.y), to_tf32(v.z), to_tf32(v.w));
}

__device__ __forceinline__ void cp_async16(void* smem_dst, const void* gmem_src) {
    uint32_t s = (uint32_t)__cvta_generic_to_shared(smem_dst);
    asm volatile("cp.async.ca.shared.global [%0], [%1], 16;\n"
                 :: "r"(s), "l"(__cvta_generic_to_global(gmem_src)) : "memory");
}
__device__ __forceinline__ void cp_commit() {
    asm volatile("cp.async.commit_group;\n" ::: "memory");
}
template <int N>
__device__ __forceinline__ void cp_wait() {
    asm volatile("cp.async.wait_group %0;\n" :: "n"(N) : "memory");
}

__device__ __forceinline__ void mma_tf32(float c[4], const uint32_t a[4],
                                         uint32_t b0, uint32_t b1) {
    asm volatile(
        "mma.sync.aligned.m16n8k8.row.col.f32.tf32.tf32.f32 "
        "{%0,%1,%2,%3}, {%4,%5,%6,%7}, {%8,%9}, {%0,%1,%2,%3};"
        : "+f"(c[0]), "+f"(c[1]), "+f"(c[2]), "+f"(c[3])
        : "r"(a[0]), "r"(a[1]), "r"(a[2]), "r"(a[3]), "r"(b0), "r"(b1));
}

template <int NT, int BST>
__device__ __forceinline__ void compute_bk(const float* __restrict__ As,
                                           const float* __restrict__ Bs,
                                           float acc[2][NT][4],
                                           int lane, int warpM, int warpN) {
    const int gid = lane >> 2, tig = lane & 3;
    #pragma unroll
    for (int kk = 0; kk < 16; kk += 8) {
        uint32_t a[2][4];
        #pragma unroll
        for (int mt = 0; mt < 2; mt++) {
            const int m = warpM + mt * 16;
            a[mt][0] = __float_as_uint(As[(m + gid)     * AST + kk + tig]);
            a[mt][1] = __float_as_uint(As[(m + gid + 8) * AST + kk + tig]);
            a[mt][2] = __float_as_uint(As[(m + gid)     * AST + kk + tig + 4]);
            a[mt][3] = __float_as_uint(As[(m + gid + 8) * AST + kk + tig + 4]);
        }
        #pragma unroll
        for (int nt = 0; nt < NT; nt++) {
            const int n = warpN + nt * 8 + gid;
            uint32_t b0 = __float_as_uint(Bs[(kk + tig)     * BST + n]);
            uint32_t b1 = __float_as_uint(Bs[(kk + tig + 4) * BST + n]);
            mma_tf32(acc[0][nt], a[0], b0, b1);
            mma_tf32(acc[1][nt], a[1], b0, b1);
        }
    }
}

// 64-deep K slab, single 16-row m-tile: acc[NT][4] (used for S = Q K^T)
template <int NT>
__device__ __forceinline__ void mma_slab64(const float* __restrict__ As, int ast,
                                           const float* __restrict__ Bs, int bst,
                                           float acc[NT][4], int lane, int rowBase) {
    const int gid = lane >> 2, tig = lane & 3;
    #pragma unroll
    for (int kk = 0; kk < 64; kk += 8) {
        uint32_t a[4];
        a[0] = __float_as_uint(As[(rowBase + gid)     * ast + kk + tig]);
        a[1] = __float_as_uint(As[(rowBase + gid + 8) * ast + kk + tig]);
        a[2] = __float_as_uint(As[(rowBase + gid)     * ast + kk + tig + 4]);
        a[3] = __float_as_uint(As[(rowBase + gid + 8) * ast + kk + tig + 4]);
        #pragma unroll
        for (int nt = 0; nt < NT; nt++) {
            uint32_t b0 = __float_as_uint(Bs[(kk + tig)     * bst + nt * 8 + gid]);
            uint32_t b1 = __float_as_uint(Bs[(kk + tig + 4) * bst + nt * 8 + gid]);
            mma_tf32(acc[nt], a, b0, b1);
        }
    }
}

// ----------------------------------------------------------------------------
// small utility kernels
// ----------------------------------------------------------------------------
__global__ void __launch_bounds__(256)
copy_tokens(const float4* __restrict__ tokens) {
    int i = blockIdx.x * 256 + threadIdx.x;
    ((float4*)g_x)[i] = tokens[i];
}

__global__ void __launch_bounds__(256)
round_w(int wSel, const float4* __restrict__ src, int n4) {
    int i = blockIdx.x * 256 + threadIdx.x;
    if (i < n4) ((float4*)selw(wSel))[i] = to_tf32_4(src[i]);
}

__global__ void __launch_bounds__(256)
kattr_build(const float* __restrict__ xy, const int* __restrict__ alive,
            const int* __restrict__ species) {
    int i = blockIdx.x * 256 + threadIdx.x;   // < ROWS
    g_kattr[i] = make_float4(xy[2 * i], xy[2 * i + 1],
                             alive[i] ? 0.f : NEGINF,
                             (species[i] < 2) ? 1.f : 0.f);
}

// ----------------------------------------------------------------------------
// LayerNorm: warp per row, float4 vectorized. roundOut -> rna-tf32 store.
// ----------------------------------------------------------------------------
__global__ void __launch_bounds__(256)
ln_kernel(int inSel, int outSel, float* __restrict__ outPtr,
          const float* __restrict__ g, const float* __restrict__ be, int roundOut) {
    const float* in = selbuf(inSel);
    float* out = (outSel == 0) ? g_h : outPtr;
    const int row = blockIdx.x * 8 + (threadIdx.x >> 5);
    const int lane = threadIdx.x & 31;
    const float4* xr = (const float4*)(in + (size_t)row * Dv);

    float4 v[4];
    #pragma unroll
    for (int i = 0; i < 4; i++) v[i] = xr[lane + 32 * i];

    float s = 0.f;
    #pragma unroll
    for (int i = 0; i < 4; i++) s += v[i].x + v[i].y + v[i].z + v[i].w;
    #pragma unroll
    for (int o = 16; o; o >>= 1) s += __shfl_xor_sync(0xffffffffu, s, o);
    const float mean = s * (1.0f / Dv);

    float q = 0.f;
    #pragma unroll
    for (int i = 0; i < 4; i++) {
        float a = v[i].x - mean, b = v[i].y - mean;
        float c = v[i].z - mean, d = v[i].w - mean;
        q += a * a + b * b + c * c + d * d;
    }
    #pragma unroll
    for (int o = 16; o; o >>= 1) q += __shfl_xor_sync(0xffffffffu, q, o);
    const float rs = rsqrtf(q * (1.0f / Dv) + 1e-5f);

    const float4* g4  = (const float4*)g;
    const float4* be4 = (const float4*)be;
    float4* o4 = (float4*)(out + (size_t)row * Dv);
    #pragma unroll
    for (int i = 0; i < 4; i++) {
        float4 gg = g4[lane + 32 * i], bb = be4[lane + 32 * i];
        float4 r;
        r.x = (v[i].x - mean) * rs * gg.x + bb.x;
        r.y = (v[i].y - mean) * rs * gg.y + bb.y;
        r.z = (v[i].z - mean) * rs * gg.z + bb.z;
        r.w = (v[i].w - mean) * rs * gg.w + bb.w;
        if (roundOut) r = to_tf32_4(r);
        o4[lane + 32 * i] = r;
    }
}

// ----------------------------------------------------------------------------
// 3-stage cp.async tensor-core NN GEMM (BN=128), single sync per BK slab.
//   EPI 0: C = rna(acc);  EPI 1: C += acc + bias;  EPI 2: C = rna(gelu(acc+bias))
// ----------------------------------------------------------------------------
template <int EPI>
__global__ void __launch_bounds__(256, 2)
gemm3(int aSel, int wSel, size_t wOff, int cSelBase, int Nn, int K,
      const float* __restrict__ bias) {
    constexpr int BN  = 128;
    constexpr int BST = BN + 8;   // 136
    constexpr int NT  = BN / 16;  // 8

    extern __shared__ float smg[];
    float* As = smg;                       // 3 * BM*AST
    float* Bs = smg + 3 * BM * AST;        // 3 * BK*BST

    const int z = blockIdx.z;
    const float* A = selbuf(aSel);
    const float* W = selw(wSel + z) + wOff;
    float* C = selbuf(cSelBase + z);

    const int tid  = threadIdx.x;
    const int lane = tid & 31;
    const int wid  = tid >> 5;
    const int warpM = (wid & 3) * 32;
    const int warpN = (wid >> 2) * (BN / 2);
    const int m0 = blockIdx.y * BM;
    const int n0 = blockIdx.x * BN;

    const int arow  = tid >> 2, ac4 = (tid & 3) * 4;
    const int arow2 = arow + 64;
    const int brow  = tid >> 5, bc = (tid & 31) * 4;

    const float* Ag = A + (size_t)m0 * K;
    const float* Bg = W + n0;

    auto load_stage = [&](int buf, int k0) {
        float* Ab = As + buf * (BM * AST);
        float* Bb = Bs + buf * (BK * BST);
        cp_async16(&Ab[arow  * AST + ac4], Ag + (size_t)arow  * K + k0 + ac4);
        cp_async16(&Ab[arow2 * AST + ac4], Ag + (size_t)arow2 * K + k0 + ac4);
        cp_async16(&Bb[brow * BST + bc],       Bg + (size_t)(k0 + brow)     * Nn + bc);
        cp_async16(&Bb[(brow + 8) * BST + bc], Bg + (size_t)(k0 + brow + 8) * Nn + bc);
        cp_commit();
    };

    float acc[2][NT][4] = {};

    load_stage(0, 0);
    load_stage(1, BK);
    const int T = K / BK;
    for (int i = 0; i < T; i++) {
        cp_wait<1>();
        __syncthreads();
        if (i + 2 < T) load_stage((i + 2) % 3, (i + 2) * BK);
        else           cp_commit();        // keep group numbering
        const int buf = i % 3;
        compute_bk<NT, BST>(As + buf * (BM * AST), Bs + buf * (BK * BST),
                            acc, lane, warpM, warpN);
    }

    const int gid = lane >> 2, tig = lane & 3;
    #pragma unroll
    for (int mt = 0; mt < 2; mt++) {
        #pragma unroll
        for (int half = 0; half < 2; half++) {
            const int row = m0 + warpM + mt * 16 + gid + half * 8;
            #pragma unroll
            for (int nt = 0; nt < NT; nt++) {
                const int col = n0 + warpN + nt * 8 + 2 * tig;
                float v0 = acc[mt][nt][half * 2 + 0];
                float v1 = acc[mt][nt][half * 2 + 1];
                float* Cp = C + (size_t)row * Nn + col;
                if (EPI == 0) {
                    Cp[0] = to_tf32(v0); Cp[1] = to_tf32(v1);
                } else if (EPI == 1) {
                    Cp[0] = Cp[0] + (v0 + bias[col]);
                    Cp[1] = Cp[1] + (v1 + bias[col + 1]);
                } else {
                    float u0 = v0 + bias[col];
                    float u1 = v1 + bias[col + 1];
                    Cp[0] = to_tf32(0.5f * u0 * (1.0f + erff(u0 * 0.70710678118654752f)));
                    Cp[1] = to_tf32(0.5f * u1 * (1.0f + erff(u1 * 0.70710678118654752f)));
                }
            }
        }
    }
}

// ----------------------------------------------------------------------------
// Flash attention v3. 128 q-rows/block, 8 warps x 16 rows, JT=64 chunks.
// Double-buffered V/attrs (cp.async) + K (register prefetch), 1 sync/chunk.
// P stays in registers; PV A-fragments built with quad shuffles.
// smem = 110,592 B -> 2 CTAs/SM.
// ----------------------------------------------------------------------------
__global__ void __launch_bounds__(256, 2)
flash_attn() {
    constexpr int QT = 128, JT = 64;
    constexpr int QST = 68, KST = 72, VST = 72;
    constexpr int KVB = JT * KST;   // 4608 floats per buffer

    extern __shared__ float sm[];
    float*  Qs = sm;                       // 128*68 = 8704
    float*  Ks = Qs + QT * QST;            // 2*4608
    float*  Vs = Ks + 2 * KVB;             // 2*4608
    float4* Ka = (float4*)(Vs + 2 * KVB);  // 2*64 float4

    const int tid = threadIdx.x, lane = tid & 31, wid = tid >> 5;
    const int gid = lane >> 2, tig = lane & 3;
    const int m0 = blockIdx.x * QT;
    const int z = blockIdx.y, bb = z >> 3, hh = z & 7;

    const float* __restrict__ Qg = g_q + (size_t)bb * Nv * Dv + hh * DHv;
    const float* __restrict__ Kg = g_k + (size_t)bb * Nv * Dv + hh * DHv;
    const float* __restrict__ Vg = g_v + (size_t)bb * Nv * Dv + hh * DHv;
    float*       __restrict__ Og = g_o + (size_t)bb * Nv * Dv + hh * DHv;
    const float4* __restrict__ kat = g_kattr + bb * Nv;

    // group 0: Q tile + V chunk 0 + attrs chunk 0
    #pragma unroll
    for (int s = 0; s < 8; s++) {
        int slot = tid + s * 256;
        int qr = slot >> 4, q4 = (slot & 15) * 4;
        cp_async16(&Qs[qr * QST + q4], Qg + (size_t)(m0 + qr) * Dv + q4);
    }
    #pragma unroll
    for (int s = 0; s < 4; s++) {
        int slot = tid + s * 256;
        int jl = slot >> 4, d4 = (slot & 15) * 4;
        cp_async16(&Vs[jl * VST + d4], Vg + (size_t)jl * Dv + d4);
    }
    if (tid < JT) cp_async16(&Ka[tid], kat + tid);
    cp_commit();

    // K chunk 0 -> registers (lane-consecutive j: conflict-free STS)
    float4 kreg[4];
    #pragma unroll
    for (int s = 0; s < 4; s++) {
        int slot = tid + s * 256;
        int jl = slot & 63, d4 = (slot >> 6) * 4;
        kreg[s] = *(const float4*)(Kg + (size_t)jl * Dv + d4);
    }

    // per-thread query attrs
    const int r0 = wid * 16 + gid, r1 = r0 + 8;
    const float4 qa0 = kat[m0 + r0];
    const float4 qa1 = kat[m0 + r1];

    float accO[8][4] = {};
    float mrow0 = -INFINITY, mrow1 = -INFINITY;
    float lrow0 = 0.f, lrow1 = 0.f;

    for (int i = 0; i < Nv / JT; i++) {
        const int buf = i & 1;
        float* Kb = Ks + buf * KVB;
        float* Vb = Vs + buf * KVB;
        const float4* Kab = Ka + buf * 64;

        // transpose-store K(i)
        #pragma unroll
        for (int s = 0; s < 4; s++) {
            int slot = tid + s * 256;
            int jl = slot & 63, d = (slot >> 6) * 4;
            Kb[(d + 0) * KST + jl] = kreg[s].x;
            Kb[(d + 1) * KST + jl] = kreg[s].y;
            Kb[(d + 2) * KST + jl] = kreg[s].z;
            Kb[(d + 3) * KST + jl] = kreg[s].w;
        }
        cp_wait<0>();          // V(i) + attrs(i) (+Q on i=0) complete
        __syncthreads();       // K(i) STS visible

        if (i + 1 < Nv / JT) {
            const int j0n = (i + 1) * JT;
            #pragma unroll
            for (int s = 0; s < 4; s++) {
                int slot = tid + s * 256;
                int jl = slot >> 4, d4 = (slot & 15) * 4;
                cp_async16(&Vs[(buf ^ 1) * KVB + jl * VST + d4],
                           Vg + (size_t)(j0n + jl) * Dv + d4);
            }
            if (tid < JT) cp_async16(&Ka[(buf ^ 1) * 64 + tid], kat + j0n + tid);
            cp_commit();
            #pragma unroll
            for (int s = 0; s < 4; s++) {
                int slot = tid + s * 256;
                int jl = slot & 63, d4 = (slot >> 6) * 4;
                kreg[s] = *(const float4*)(Kg + (size_t)(j0n + jl) * Dv + d4);
            }
        }

        // S = Q K^T for this warp's 16 rows
        float accS[8][4] = {};
        mma_slab64<8>(Qs, QST, Kb, KST, accS, lane, wid * 16);

        // bias + chunk max
        float mc0 = -INFINITY, mc1 = -INFINITY;
        #pragma unroll
        for (int nt = 0; nt < 8; nt++) {
            #pragma unroll
            for (int c = 0; c < 2; c++) {
                int jl = nt * 8 + 2 * tig + c;
                float4 ka = Kab[jl];
                float b0 = ka.z, b1 = ka.z;
                float dx0 = qa0.x - ka.x, dy0 = qa0.y - ka.y;
                float dx1 = qa1.x - ka.x, dy1 = qa1.y - ka.y;
                if (dx0 * dx0 + dy0 * dy0 > R2) b0 += NEGINF;
                if (qa0.w != ka.w)              b0 += NEGINF;
                if (dx1 * dx1 + dy1 * dy1 > R2) b1 += NEGINF;
                if (qa1.w != ka.w)              b1 += NEGINF;
                float s0 = accS[nt][c]     * 0.125f + b0;
                float s1 = accS[nt][c + 2] * 0.125f + b1;
                accS[nt][c]     = s0; mc0 = fmaxf(mc0, s0);
                accS[nt][c + 2] = s1; mc1 = fmaxf(mc1, s1);
            }
        }
        mc0 = fmaxf(mc0, __shfl_xor_sync(0xffffffffu, mc0, 1));
        mc0 = fmaxf(mc0, __shfl_xor_sync(0xffffffffu, mc0, 2));
        mc1 = fmaxf(mc1, __shfl_xor_sync(0xffffffffu, mc1, 1));
        mc1 = fmaxf(mc1, __shfl_xor_sync(0xffffffffu, mc1, 2));

        float mn0 = fmaxf(mrow0, mc0), mn1 = fmaxf(mrow1, mc1);
        float sc0 = __expf(mrow0 - mn0), sc1 = __expf(mrow1 - mn1);

        // exponentiate in place, accumulate row sums
        float sum0 = 0.f, sum1 = 0.f;
        #pragma unroll
        for (int nt = 0; nt < 8; nt++) {
            float p0 = __expf(accS[nt][0] - mn0);
            float p1 = __expf(accS[nt][1] - mn0);
            float p2 = __expf(accS[nt][2] - mn1);
            float p3 = __expf(accS[nt][3] - mn1);
            accS[nt][0] = p0; accS[nt][1] = p1;
            accS[nt][2] = p2; accS[nt][3] = p3;
            sum0 += p0 + p1; sum1 += p2 + p3;
        }
        sum0 += __shfl_xor_sync(0xffffffffu, sum0, 1);
        sum0 += __shfl_xor_sync(0xffffffffu, sum0, 2);
        sum1 += __shfl_xor_sync(0xffffffffu, sum1, 1);
        sum1 += __shfl_xor_sync(0xffffffffu, sum1, 2);

        lrow0 = lrow0 * sc0 + sum0;
        lrow1 = lrow1 * sc1 + sum1;
        mrow0 = mn0; mrow1 = mn1;

        #pragma unroll
        for (int dt = 0; dt < 8; dt++) {
            accO[dt][0] *= sc0; accO[dt][1] *= sc0;
            accO[dt][2] *= sc1; accO[dt][3] *= sc1;
        }

        // PV: build A-fragments from register P via quad shuffles.
        // c-frag (row gid, cols 2*tig,2*tig+1) -> a-frag (cols tig, tig+4).
        const int src1 = (lane & ~3) | (tig >> 1);
        const int src2 = src1 + 2;
        const bool odd = tig & 1;
        #pragma unroll
        for (int nt = 0; nt < 8; nt++) {    // k-slab over j = nt*8..+8
            float x0 = __shfl_sync(0xffffffffu, accS[nt][0], src1);
            float y0 = __shfl_sync(0xffffffffu, accS[nt][1], src1);
            float x1 = __shfl_sync(0xffffffffu, accS[nt][2], src1);
            float y1 = __shfl_sync(0xffffffffu, accS[nt][3], src1);
            float x2 = __shfl_sync(0xffffffffu, accS[nt][0], src2);
            float y2 = __shfl_sync(0xffffffffu, accS[nt][1], src2);
            float x3 = __shfl_sync(0xffffffffu, accS[nt][2], src2);
            float y3 = __shfl_sync(0xffffffffu, accS[nt][3], src2);
            uint32_t a[4];
            a[0] = __float_as_uint(odd ? y0 : x0);   // (row gid,   k=tig)
            a[1] = __float_as_uint(odd ? y1 : x1);   // (row gid+8, k=tig)
            a[2] = __float_as_uint(odd ? y2 : x2);   // (row gid,   k=tig+4)
            a[3] = __float_as_uint(odd ? y3 : x3);   // (row gid+8, k=tig+4)
            #pragma unroll
            for (int dt = 0; dt < 8; dt++) {
                uint32_t b0 = __float_as_uint(Vb[(nt * 8 + tig)     * VST + dt * 8 + gid]);
                uint32_t b1 = __float_as_uint(Vb[(nt * 8 + tig + 4) * VST + dt * 8 + gid]);
                mma_tf32(accO[dt], a, b0, b1);
            }
        }
    }

    // epilogue: normalize, rna-round (O feeds Wo GEMM A-operand), store
    float il0 = 1.f / lrow0, il1 = 1.f / lrow1;
    #pragma unroll
    for (int dt = 0; dt < 8; dt++) {
        int col = dt * 8 + 2 * tig;
        float* o0 = Og + (size_t)(m0 + r0) * Dv + col;
        float* o1 = Og + (size_t)(m0 + r1) * Dv + col;
        o0[0] = to_tf32(accO[dt][0] * il0); o0[1] = to_tf32(accO[dt][1] * il0);
        o1[0] = to_tf32(accO[dt][2] * il1); o1[1] = to_tf32(accO[dt][3] * il1);
    }
}

// ============================================================================
// Launch sequence
// ============================================================================
extern "C" void kernel_launch(void* const* d_in, const int* in_sizes, int n_in,
                              void* d_out, int out_size) {
    const float* tokens = (const float*)d_in[0];
    const float* xy     = (const float*)d_in[1];
    const float* Wq     = (const float*)d_in[2];
    const float* Wk     = (const float*)d_in[3];
    const float* Wv     = (const float*)d_in[4];
    const float* Wo     = (const float*)d_in[5];
    const float* bo     = (const float*)d_in[6];
    const float* W1     = (const float*)d_in[7];
    const float* b1     = (const float*)d_in[8];
    const float* W2     = (const float*)d_in[9];
    const float* b2     = (const float*)d_in[10];
    const float* g1     = (const float*)d_in[11];
    const float* be1    = (const float*)d_in[12];
    const float* g2     = (const float*)d_in[13];
    const float* be2    = (const float*)d_in[14];
    const float* gf     = (const float*)d_in[15];
    const float* bf     = (const float*)d_in[16];
    const int*   alive  = (const int*)d_in[17];
    const int*   species= (const int*)d_in[18];
    float* out = (float*)d_out;

    constexpr int GS128 = 3 * (BM * AST + BK * 136) * 4;   // 56832
    constexpr int FLASH_SMEM = (128 * 68 + 64 * 72 * 4) * 4 + 2 * 64 * 16; // 110592

    cudaFuncSetAttribute(gemm3<0>, cudaFuncAttributeMaxDynamicSharedMemorySize, GS128);
    cudaFuncSetAttribute(gemm3<1>, cudaFuncAttributeMaxDynamicSharedMemorySize, GS128);
    cudaFuncSetAttribute(gemm3<2>, cudaFuncAttributeMaxDynamicSharedMemorySize, GS128);
    cudaFuncSetAttribute(flash_attn, cudaFuncAttributeMaxDynamicSharedMemorySize, FLASH_SMEM);

    // rna-round weights once per launch
    {
        int n4a = Lv * Dv * Dv / 4;
        int n4b = Lv * Dv * DFFv / 4;
        round_w<<<(n4a + 255) / 256, 256>>>(0, (const float4*)Wq, n4a);
        round_w<<<(n4a + 255) / 256, 256>>>(1, (const float4*)Wk, n4a);
        round_w<<<(n4a + 255) / 256, 256>>>(2, (const float4*)Wv, n4a);
        round_w<<<(n4a + 255) / 256, 256>>>(3, (const float4*)Wo, n4a);
        round_w<<<(n4b + 255) / 256, 256>>>(4, (const float4*)W1, n4b);
        round_w<<<(n4b + 255) / 256, 256>>>(5, (const float4*)W2, n4b);
    }
    kattr_build<<<ROWS / 256, 256>>>(xy, alive, species);
    copy_tokens<<<(ROWS * Dv / 4) / 256, 256>>>((const float4*)tokens);

    for (int l = 0; l < Lv; l++) {
        const size_t oD = (size_t)l * Dv * Dv;
        const size_t oF = (size_t)l * Dv * DFFv;
        // ln1: x -> h (rounded)
        ln_kernel<<<ROWS / 8, 256>>>(6, 0, nullptr, g1 + l * Dv, be1 + l * Dv, 1);
        // fused QKV
        gemm3<0><<<dim3(Dv / 128, ROWS / 128, 3), 256, GS128>>>(
            0, 0, oD, 3, Dv, Dv, nullptr);
        // flash attention -> o (rounded)
        flash_attn<<<dim3(Nv / 128, Bv * 8), 256, FLASH_SMEM>>>();
        // x += o Wo + bo
        gemm3<1><<<dim3(Dv / 128, ROWS / 128, 1), 256, GS128>>>(
            1, 3, oD, 6, Dv, Dv, bo + l * Dv);
        // ln2: x -> h (rounded)
        ln_kernel<<<ROWS / 8, 256>>>(6, 0, nullptr, g2 + l * Dv, be2 + l * Dv, 1);
        // ff = gelu(h W1 + b1) (rounded)
        gemm3<2><<<dim3(DFFv / 128, ROWS / 128, 1), 256, GS128>>>(
            0, 4, oF, 2, DFFv, Dv, b1 + l * DFFv);
        // x += ff W2 + b2
        gemm3<1><<<dim3(Dv / 128, ROWS / 128, 1), 256, GS128>>>(
            2, 5, oF, 6, Dv, DFFv, b2 + l * Dv);
    }

    // final layernorm -> out (full fp32)
    ln_kernel<<<ROWS / 8, 256>>>(6, 1, out, gf, bf, 0);
}

// round 7
// speedup vs baseline: 1.1584x; 1.0485x over previous
#include <cuda_runtime.h>
#include <math.h>
#include <stdint.h>

// ============================================================================
// EcosystemTransformer — tf32 mma; K produced pre-transposed (+Q pre-scaled)
// by the QKV GEMM epilogue; flash attn is pure cp.async double-buffered.
//   B=4, N=1024, D=512, H=8, L=6, DFF=2048, DH=64
// ============================================================================

namespace {
constexpr int Bv   = 4;
constexpr int Nv   = 1024;
constexpr int Dv   = 512;
constexpr int Lv   = 6;
constexpr int DFFv = 2048;
constexpr int DHv  = 64;
constexpr int ROWS = Bv * Nv;           // 4096
constexpr float NEGINF = -1000000000.0f;
constexpr float R2 = 100.0f;

constexpr int BM  = 128;
constexpr int BK  = 16;
constexpr int AST = 20;
}

// Scratch buffers
__device__ __align__(16) float g_x [ROWS * Dv];
__device__ __align__(16) float g_h [ROWS * Dv];
__device__ __align__(16) float g_q [ROWS * Dv];
__device__ __align__(16) float g_k [ROWS * Dv];        // unused (K lives in g_kT)
__device__ __align__(16) float g_v [ROWS * Dv];
__device__ __align__(16) float g_o [ROWS * Dv];
__device__ __align__(16) float g_ff[ROWS * DFFv];
__device__ __align__(16) float g_kT[32 * DHv * Nv];    // [b*8+h][d][j]
__device__ __align__(16) float4 g_kattr[ROWS];         // (x, y, deadbias, isagent)

// rna-rounded tf32 weight copies
__device__ __align__(16) float g_Wq[Lv * Dv * Dv];
__device__ __align__(16) float g_Wk[Lv * Dv * Dv];
__device__ __align__(16) float g_Wv[Lv * Dv * Dv];
__device__ __align__(16) float g_Wo[Lv * Dv * Dv];
__device__ __align__(16) float g_W1[Lv * Dv * DFFv];
__device__ __align__(16) float g_W2[Lv * DFFv * Dv];

__device__ __forceinline__ float* selbuf(int s) {
    switch (s) {
        case 0: return g_h;
        case 1: return g_o;
        case 2: return g_ff;
        case 3: return g_q;
        case 4: return g_k;
        case 5: return g_v;
        default: return g_x;
    }
}
__device__ __forceinline__ float* selw(int s) {
    switch (s) {
        case 0: return g_Wq;
        case 1: return g_Wk;
        case 2: return g_Wv;
        case 3: return g_Wo;
        case 4: return g_W1;
        default: return g_W2;
    }
}

// ---------------------------------------------------------------------------
// helpers
// ---------------------------------------------------------------------------
__device__ __forceinline__ float to_tf32(float x) {
    uint32_t u;
    asm("cvt.rna.tf32.f32 %0, %1;" : "=r"(u) : "f"(x));
    return __uint_as_float(u);
}
__device__ __forceinline__ float4 to_tf32_4(float4 v) {
    return make_float4(to_tf32(v.x), to_tf32(v.y), to_tf32(v.z), to_tf32(v.w));
}

__device__ __forceinline__ void cp_async16(void* smem_dst, const void* gmem_src) {
    uint32_t s = (uint32_t)__cvta_generic_to_shared(smem_dst);
    asm volatile("cp.async.ca.shared.global [%0], [%1], 16;\n"
                 :: "r"(s), "l"(__cvta_generic_to_global(gmem_src)) : "memory");
}
__device__ __forceinline__ void cp_commit() {
    asm volatile("cp.async.commit_group;\n" ::: "memory");
}
template <int N>
__device__ __forceinline__ void cp_wait() {
    asm volatile("cp.async.wait_group %0;\n" :: "n"(N) : "memory");
}

__device__ __forceinline__ void mma_tf32(float c[4], const uint32_t a[4],
                                         uint32_t b0, uint32_t b1) {
    asm volatile(
        "mma.sync.aligned.m16n8k8.row.col.f32.tf32.tf32.f32 "
        "{%0,%1,%2,%3}, {%4,%5,%6,%7}, {%8,%9}, {%0,%1,%2,%3};"
        : "+f"(c[0]), "+f"(c[1]), "+f"(c[2]), "+f"(c[3])
        : "r"(a[0]), "r"(a[1]), "r"(a[2]), "r"(a[3]), "r"(b0), "r"(b1));
}

template <int NT, int BST>
__device__ __forceinline__ void compute_bk(const float* __restrict__ As,
                                           const float* __restrict__ Bs,
                                           float acc[2][NT][4],
                                           int lane, int warpM, int warpN) {
    const int gid = lane >> 2, tig = lane & 3;
    #pragma unroll
    for (int kk = 0; kk < 16; kk += 8) {
        uint32_t a[2][4];
        #pragma unroll
        for (int mt = 0; mt < 2; mt++) {
            const int m = warpM + mt * 16;
            a[mt][0] = __float_as_uint(As[(m + gid)     * AST + kk + tig]);
            a[mt][1] = __float_as_uint(As[(m + gid + 8) * AST + kk + tig]);
            a[mt][2] = __float_as_uint(As[(m + gid)     * AST + kk + tig + 4]);
            a[mt][3] = __float_as_uint(As[(m + gid + 8) * AST + kk + tig + 4]);
        }
        #pragma unroll
        for (int nt = 0; nt < NT; nt++) {
            const int n = warpN + nt * 8 + gid;
            uint32_t b0 = __float_as_uint(Bs[(kk + tig)     * BST + n]);
            uint32_t b1 = __float_as_uint(Bs[(kk + tig + 4) * BST + n]);
            mma_tf32(acc[0][nt], a[0], b0, b1);
            mma_tf32(acc[1][nt], a[1], b0, b1);
        }
    }
}

// 64-deep K slab, single 16-row m-tile: acc[NT][4] (used for S = Q K^T)
template <int NT>
__device__ __forceinline__ void mma_slab64(const float* __restrict__ As, int ast,
                                           const float* __restrict__ Bs, int bst,
                                           float acc[NT][4], int lane, int rowBase) {
    const int gid = lane >> 2, tig = lane & 3;
    #pragma unroll
    for (int kk = 0; kk < 64; kk += 8) {
        uint32_t a[4];
        a[0] = __float_as_uint(As[(rowBase + gid)     * ast + kk + tig]);
        a[1] = __float_as_uint(As[(rowBase + gid + 8) * ast + kk + tig]);
        a[2] = __float_as_uint(As[(rowBase + gid)     * ast + kk + tig + 4]);
        a[3] = __float_as_uint(As[(rowBase + gid + 8) * ast + kk + tig + 4]);
        #pragma unroll
        for (int nt = 0; nt < NT; nt++) {
            uint32_t b0 = __float_as_uint(Bs[(kk + tig)     * bst + nt * 8 + gid]);
            uint32_t b1 = __float_as_uint(Bs[(kk + tig + 4) * bst + nt * 8 + gid]);
            mma_tf32(acc[nt], a, b0, b1);
        }
    }
}

// ----------------------------------------------------------------------------
// small utility kernels
// ----------------------------------------------------------------------------
__global__ void __launch_bounds__(256)
copy_tokens(const float4* __restrict__ tokens) {
    int i = blockIdx.x * 256 + threadIdx.x;
    ((float4*)g_x)[i] = tokens[i];
}

// all six weights in one launch; blockIdx.y selects the weight
__global__ void __launch_bounds__(256)
round_w_all(const float4* __restrict__ Wq, const float4* __restrict__ Wk,
            const float4* __restrict__ Wv, const float4* __restrict__ Wo,
            const float4* __restrict__ W1, const float4* __restrict__ W2) {
    const int y = blockIdx.y;
    const int n4a = Lv * Dv * Dv / 4;
    const int n4b = Lv * Dv * DFFv / 4;
    const int n4 = (y < 4) ? n4a : n4b;
    int i = blockIdx.x * 256 + threadIdx.x;
    if (i >= n4) return;
    const float4* src = (y == 0) ? Wq : (y == 1) ? Wk : (y == 2) ? Wv
                       : (y == 3) ? Wo : (y == 4) ? W1 : W2;
    ((float4*)selw(y))[i] = to_tf32_4(src[i]);
}

__global__ void __launch_bounds__(256)
kattr_build(const float* __restrict__ xy, const int* __restrict__ alive,
            const int* __restrict__ species) {
    int i = blockIdx.x * 256 + threadIdx.x;   // < ROWS
    g_kattr[i] = make_float4(xy[2 * i], xy[2 * i + 1],
                             alive[i] ? 0.f : NEGINF,
                             (species[i] < 2) ? 1.f : 0.f);
}

// ----------------------------------------------------------------------------
// LayerNorm: warp per row, float4 vectorized. roundOut -> rna-tf32 store.
// ----------------------------------------------------------------------------
__global__ void __launch_bounds__(256)
ln_kernel(int inSel, int outSel, float* __restrict__ outPtr,
          const float* __restrict__ g, const float* __restrict__ be, int roundOut) {
    const float* in = selbuf(inSel);
    float* out = (outSel == 0) ? g_h : outPtr;
    const int row = blockIdx.x * 8 + (threadIdx.x >> 5);
    const int lane = threadIdx.x & 31;
    const float4* xr = (const float4*)(in + (size_t)row * Dv);

    float4 v[4];
    #pragma unroll
    for (int i = 0; i < 4; i++) v[i] = xr[lane + 32 * i];

    float s = 0.f;
    #pragma unroll
    for (int i = 0; i < 4; i++) s += v[i].x + v[i].y + v[i].z + v[i].w;
    #pragma unroll
    for (int o = 16; o; o >>= 1) s += __shfl_xor_sync(0xffffffffu, s, o);
    const float mean = s * (1.0f / Dv);

    float q = 0.f;
    #pragma unroll
    for (int i = 0; i < 4; i++) {
        float a = v[i].x - mean, b = v[i].y - mean;
        float c = v[i].z - mean, d = v[i].w - mean;
        q += a * a + b * b + c * c + d * d;
    }
    #pragma unroll
    for (int o = 16; o; o >>= 1) q += __shfl_xor_sync(0xffffffffu, q, o);
    const float rs = rsqrtf(q * (1.0f / Dv) + 1e-5f);

    const float4* g4  = (const float4*)g;
    const float4* be4 = (const float4*)be;
    float4* o4 = (float4*)(out + (size_t)row * Dv);
    #pragma unroll
    for (int i = 0; i < 4; i++) {
        float4 gg = g4[lane + 32 * i], bb = be4[lane + 32 * i];
        float4 r;
        r.x = (v[i].x - mean) * rs * gg.x + bb.x;
        r.y = (v[i].y - mean) * rs * gg.y + bb.y;
        r.z = (v[i].z - mean) * rs * gg.z + bb.z;
        r.w = (v[i].w - mean) * rs * gg.w + bb.w;
        if (roundOut) r = to_tf32_4(r);
        o4[lane + 32 * i] = r;
    }
}

// ----------------------------------------------------------------------------
// 3-stage cp.async tensor-core NN GEMM (BM=128, BN=128).
//   EPI 0 (QKV): z=0 -> g_q rounded * 0.125; z=1 -> g_kT transposed rounded;
//                z=2 -> g_v rounded.
//   EPI 1: C += acc + bias;  EPI 2: C = rna(gelu(acc + bias))
// ----------------------------------------------------------------------------
template <int EPI>
__global__ void __launch_bounds__(256, 2)
gemm3(int aSel, int wSel, size_t wOff, int cSelBase, int Nn, int K,
      const float* __restrict__ bias) {
    constexpr int BN  = 128;
    constexpr int BST = BN + 8;   // 136
    constexpr int NT  = BN / 16;  // 8

    extern __shared__ float smg[];
    float* As = smg;
    float* Bs = smg + 3 * BM * AST;

    const int z = blockIdx.z;
    const float* A = selbuf(aSel);
    const float* W = selw(wSel + z) + wOff;
    float* C = selbuf(cSelBase + z);

    const int tid  = threadIdx.x;
    const int lane = tid & 31;
    const int wid  = tid >> 5;
    const int warpM = (wid & 3) * 32;
    const int warpN = (wid >> 2) * (BN / 2);
    const int m0 = blockIdx.y * BM;
    const int n0 = blockIdx.x * BN;

    const int arow  = tid >> 2, ac4 = (tid & 3) * 4;
    const int arow2 = arow + 64;
    const int brow  = tid >> 5, bc = (tid & 31) * 4;

    const float* Ag = A + (size_t)m0 * K;
    const float* Bg = W + n0;

    auto load_stage = [&](int buf, int k0) {
        float* Ab = As + buf * (BM * AST);
        float* Bb = Bs + buf * (BK * BST);
        cp_async16(&Ab[arow  * AST + ac4], Ag + (size_t)arow  * K + k0 + ac4);
        cp_async16(&Ab[arow2 * AST + ac4], Ag + (size_t)arow2 * K + k0 + ac4);
        cp_async16(&Bb[brow * BST + bc],       Bg + (size_t)(k0 + brow)     * Nn + bc);
        cp_async16(&Bb[(brow + 8) * BST + bc], Bg + (size_t)(k0 + brow + 8) * Nn + bc);
        cp_commit();
    };

    float acc[2][NT][4] = {};

    load_stage(0, 0);
    load_stage(1, BK);
    const int T = K / BK;
    for (int i = 0; i < T; i++) {
        cp_wait<1>();
        __syncthreads();
        if (i + 2 < T) load_stage((i + 2) % 3, (i + 2) * BK);
        else           cp_commit();
        const int buf = i % 3;
        compute_bk<NT, BST>(As + buf * (BM * AST), Bs + buf * (BK * BST),
                            acc, lane, warpM, warpN);
    }

    const int gid = lane >> 2, tig = lane & 3;
    #pragma unroll
    for (int mt = 0; mt < 2; mt++) {
        #pragma unroll
        for (int half = 0; half < 2; half++) {
            const int row = m0 + warpM + mt * 16 + gid + half * 8;
            #pragma unroll
            for (int nt = 0; nt < NT; nt++) {
                const int col = n0 + warpN + nt * 8 + 2 * tig;
                float v0 = acc[mt][nt][half * 2 + 0];
                float v1 = acc[mt][nt][half * 2 + 1];
                if (EPI == 0) {
                    if (z == 1) {
                        // K: write transposed into g_kT[b*8+h][d][j]
                        const int bbk = row >> 10, j = row & 1023;
                        const int hh = col >> 6, d = col & 63;
                        float* dst = g_kT + (((size_t)(bbk * 8 + hh) * DHv + d) << 10) + j;
                        dst[0]    = to_tf32(v0);
                        dst[1024] = to_tf32(v1);   // d+1 row
                    } else {
                        const float sc = (z == 0) ? 0.125f : 1.0f;
                        float* Cp = C + (size_t)row * Nn + col;
                        Cp[0] = to_tf32(v0 * sc); Cp[1] = to_tf32(v1 * sc);
                    }
                } else if (EPI == 1) {
                    float* Cp = C + (size_t)row * Nn + col;
                    Cp[0] = Cp[0] + (v0 + bias[col]);
                    Cp[1] = Cp[1] + (v1 + bias[col + 1]);
                } else {
                    float* Cp = C + (size_t)row * Nn + col;
                    float u0 = v0 + bias[col];
                    float u1 = v1 + bias[col + 1];
                    Cp[0] = to_tf32(0.5f * u0 * (1.0f + erff(u0 * 0.70710678118654752f)));
                    Cp[1] = to_tf32(0.5f * u1 * (1.0f + erff(u1 * 0.70710678118654752f)));
                }
            }
        }
    }
}

// ----------------------------------------------------------------------------
// BM=64 x BN=128 GEMM (residual epilogue) for Wo / FFN2: grid fills the chip.
// 8 warps as 2(M) x 4(N), warp tile 32x32 (NT=4).
// ----------------------------------------------------------------------------
__global__ void __launch_bounds__(256, 2)
gemm64(int aSel, int wSel, size_t wOff, int Nn, int K,
       const float* __restrict__ bias) {
    constexpr int BM2 = 64;
    constexpr int BN  = 128;
    constexpr int BST = BN + 8;
    constexpr int NT  = 4;

    extern __shared__ float smg[];
    float* As = smg;                         // 3 * 64*20
    float* Bs = smg + 3 * BM2 * AST;         // 3 * 16*136

    const float* A = selbuf(aSel);
    const float* W = selw(wSel) + wOff;
    float* C = selbuf(6);                    // g_x (residual target)

    const int tid  = threadIdx.x;
    const int lane = tid & 31;
    const int wid  = tid >> 5;
    const int warpM = (wid & 1) * 32;
    const int warpN = (wid >> 1) * 32;
    const int m0 = blockIdx.y * BM2;
    const int n0 = blockIdx.x * BN;

    const int arow = tid >> 2, ac4 = (tid & 3) * 4;
    const int brow = tid >> 5, bc = (tid & 31) * 4;

    const float* Ag = A + (size_t)m0 * K;
    const float* Bg = W + n0;

    auto load_stage = [&](int buf, int k0) {
        float* Ab = As + buf * (BM2 * AST);
        float* Bb = Bs + buf * (BK * BST);
        cp_async16(&Ab[arow * AST + ac4], Ag + (size_t)arow * K + k0 + ac4);
        cp_async16(&Bb[brow * BST + bc],       Bg + (size_t)(k0 + brow)     * Nn + bc);
        cp_async16(&Bb[(brow + 8) * BST + bc], Bg + (size_t)(k0 + brow + 8) * Nn + bc);
        cp_commit();
    };

    float acc[2][NT][4] = {};

    load_stage(0, 0);
    load_stage(1, BK);
    const int T = K / BK;
    for (int i = 0; i < T; i++) {
        cp_wait<1>();
        __syncthreads();
        if (i + 2 < T) load_stage((i + 2) % 3, (i + 2) * BK);
        else           cp_commit();
        const int buf = i % 3;
        compute_bk<NT, BST>(As + buf * (BM2 * AST), Bs + buf * (BK * BST),
                            acc, lane, warpM, warpN);
    }

    const int gid = lane >> 2, tig = lane & 3;
    #pragma unroll
    for (int mt = 0; mt < 2; mt++) {
        #pragma unroll
        for (int half = 0; half < 2; half++) {
            const int row = m0 + warpM + mt * 16 + gid + half * 8;
            #pragma unroll
            for (int nt = 0; nt < NT; nt++) {
                const int col = n0 + warpN + nt * 8 + 2 * tig;
                float* Cp = C + (size_t)row * Nn + col;
                Cp[0] = Cp[0] + (acc[mt][nt][half * 2 + 0] + bias[col]);
                Cp[1] = Cp[1] + (acc[mt][nt][half * 2 + 1] + bias[col + 1]);
            }
        }
    }
}

// ----------------------------------------------------------------------------
// Flash attention v4: K pre-transposed in gmem; everything via cp.async
// double-buffer; register P with quad-shuffle fragment conversion.
// ----------------------------------------------------------------------------
__global__ void __launch_bounds__(256, 2)
flash_attn() {
    constexpr int QT = 128, JT = 64;
    constexpr int QST = 68, KST = 72, VST = 72;
    constexpr int KVB = JT * KST;   // 4608

    extern __shared__ float sm[];
    float*  Qs = sm;                       // 128*68 = 8704
    float*  Ks = Qs + QT * QST;            // 2*4608  ([d][j])
    float*  Vs = Ks + 2 * KVB;             // 2*4608  ([j][d])
    float4* Ka = (float4*)(Vs + 2 * KVB);  // 2*64

    const int tid = threadIdx.x, lane = tid & 31, wid = tid >> 5;
    const int gid = lane >> 2, tig = lane & 3;
    const int m0 = blockIdx.x * QT;
    const int z = blockIdx.y, bb = z >> 3, hh = z & 7;

    const float* __restrict__ Qg  = g_q + (size_t)bb * Nv * Dv + hh * DHv;
    const float* __restrict__ KTg = g_kT + (size_t)z * DHv * Nv;
    const float* __restrict__ Vg  = g_v + (size_t)bb * Nv * Dv + hh * DHv;
    float*       __restrict__ Og  = g_o + (size_t)bb * Nv * Dv + hh * DHv;
    const float4* __restrict__ kat = g_kattr + bb * Nv;

    auto load_chunk = [&](int buf, int j0) {
        #pragma unroll
        for (int s = 0; s < 4; s++) {
            int slot = tid + s * 256;
            int r = slot >> 4, c4 = (slot & 15) * 4;
            // K^T: row = d (64 rows), cols j0..j0+63
            cp_async16(&Ks[buf * KVB + r * KST + c4], KTg + ((size_t)r << 10) + j0 + c4);
            // V: row = j, cols d
            cp_async16(&Vs[buf * KVB + r * VST + c4], Vg + (size_t)(j0 + r) * Dv + c4);
        }
        if (tid < JT) cp_async16(&Ka[buf * 64 + tid], kat + j0 + tid);
        cp_commit();
    };

    // group 0: Q tile + chunk 0
    #pragma unroll
    for (int s = 0; s < 8; s++) {
        int slot = tid + s * 256;
        int qr = slot >> 4, q4 = (slot & 15) * 4;
        cp_async16(&Qs[qr * QST + q4], Qg + (size_t)(m0 + qr) * Dv + q4);
    }
    load_chunk(0, 0);

    const int r0 = wid * 16 + gid, r1 = r0 + 8;
    const float4 qa0 = kat[m0 + r0];
    const float4 qa1 = kat[m0 + r1];

    float accO[8][4] = {};
    float mrow0 = -INFINITY, mrow1 = -INFINITY;
    float lrow0 = 0.f, lrow1 = 0.f;

    for (int i = 0; i < Nv / JT; i++) {
        const int buf = i & 1;
        float* Kb = Ks + buf * KVB;
        float* Vb = Vs + buf * KVB;
        const float4* Kab = Ka + buf * 64;

        cp_wait<0>();       // chunk i (and Q on i=0) complete
        __syncthreads();    // all threads past reads of buf^1 (chunk i-1)

        if (i + 1 < Nv / JT) load_chunk(buf ^ 1, (i + 1) * JT);

        // S = Q K^T  (Q pre-scaled by 0.125)
        float accS[8][4] = {};
        mma_slab64<8>(Qs, QST, Kb, KST, accS, lane, wid * 16);

        // bias + chunk max
        float mc0 = -INFINITY, mc1 = -INFINITY;
        #pragma unroll
        for (int nt = 0; nt < 8; nt++) {
            #pragma unroll
            for (int c = 0; c < 2; c++) {
                int jl = nt * 8 + 2 * tig + c;
                float4 ka = Kab[jl];
                float b0 = ka.z, b1 = ka.z;
                float dx0 = qa0.x - ka.x, dy0 = qa0.y - ka.y;
                float dx1 = qa1.x - ka.x, dy1 = qa1.y - ka.y;
                if (dx0 * dx0 + dy0 * dy0 > R2) b0 += NEGINF;
                if (qa0.w != ka.w)              b0 += NEGINF;
                if (dx1 * dx1 + dy1 * dy1 > R2) b1 += NEGINF;
                if (qa1.w != ka.w)              b1 += NEGINF;
                float s0 = accS[nt][c]     + b0;
                float s1 = accS[nt][c + 2] + b1;
                accS[nt][c]     = s0; mc0 = fmaxf(mc0, s0);
                accS[nt][c + 2] = s1; mc1 = fmaxf(mc1, s1);
            }
        }
        mc0 = fmaxf(mc0, __shfl_xor_sync(0xffffffffu, mc0, 1));
        mc0 = fmaxf(mc0, __shfl_xor_sync(0xffffffffu, mc0, 2));
        mc1 = fmaxf(mc1, __shfl_xor_sync(0xffffffffu, mc1, 1));
        mc1 = fmaxf(mc1, __shfl_xor_sync(0xffffffffu, mc1, 2));

        float mn0 = fmaxf(mrow0, mc0), mn1 = fmaxf(mrow1, mc1);
        float sc0 = __expf(mrow0 - mn0), sc1 = __expf(mrow1 - mn1);

        float sum0 = 0.f, sum1 = 0.f;
        #pragma unroll
        for (int nt = 0; nt < 8; nt++) {
            float p0 = __expf(accS[nt][0] - mn0);
            float p1 = __expf(accS[nt][1] - mn0);
            float p2 = __expf(accS[nt][2] - mn1);
            float p3 = __expf(accS[nt][3] - mn1);
            accS[nt][0] = p0; accS[nt][1] = p1;
            accS[nt][2] = p2; accS[nt][3] = p3;
            sum0 += p0 + p1; sum1 += p2 + p3;
        }
        sum0 += __shfl_xor_sync(0xffffffffu, sum0, 1);
        sum0 += __shfl_xor_sync(0xffffffffu, sum0, 2);
        sum1 += __shfl_xor_sync(0xffffffffu, sum1, 1);
        sum1 += __shfl_xor_sync(0xffffffffu, sum1, 2);

        lrow0 = lrow0 * sc0 + sum0;
        lrow1 = lrow1 * sc1 + sum1;
        mrow0 = mn0; mrow1 = mn1;

        #pragma unroll
        for (int dt = 0; dt < 8; dt++) {
            accO[dt][0] *= sc0; accO[dt][1] *= sc0;
            accO[dt][2] *= sc1; accO[dt][3] *= sc1;
        }

        // PV: A-fragments from register P via quad shuffles
        const int src1 = (lane & ~3) | (tig >> 1);
        const int src2 = src1 + 2;
        const bool odd = tig & 1;
        #pragma unroll
        for (int nt = 0; nt < 8; nt++) {
            float x0 = __shfl_sync(0xffffffffu, accS[nt][0], src1);
            float y0 = __shfl_sync(0xffffffffu, accS[nt][1], src1);
            float x1 = __shfl_sync(0xffffffffu, accS[nt][2], src1);
            float y1 = __shfl_sync(0xffffffffu, accS[nt][3], src1);
            float x2 = __shfl_sync(0xffffffffu, accS[nt][0], src2);
            float y2 = __shfl_sync(0xffffffffu, accS[nt][1], src2);
            float x3 = __shfl_sync(0xffffffffu, accS[nt][2], src2);
            float y3 = __shfl_sync(0xffffffffu, accS[nt][3], src2);
            uint32_t a[4];
            a[0] = __float_as_uint(odd ? y0 : x0);
            a[1] = __float_as_uint(odd ? y1 : x1);
            a[2] = __float_as_uint(odd ? y2 : x2);
            a[3] = __float_as_uint(odd ? y3 : x3);
            #pragma unroll
            for (int dt = 0; dt < 8; dt++) {
                uint32_t b0 = __float_as_uint(Vb[(nt * 8 + tig)     * VST + dt * 8 + gid]);
                uint32_t b1 = __float_as_uint(Vb[(nt * 8 + tig + 4) * VST + dt * 8 + gid]);
                mma_tf32(accO[dt], a, b0, b1);
            }
        }
    }

    float il0 = 1.f / lrow0, il1 = 1.f / lrow1;
    #pragma unroll
    for (int dt = 0; dt < 8; dt++) {
        int col = dt * 8 + 2 * tig;
        float* o0 = Og + (size_t)(m0 + r0) * Dv + col;
        float* o1 = Og + (size_t)(m0 + r1) * Dv + col;
        o0[0] = to_tf32(accO[dt][0] * il0); o0[1] = to_tf32(accO[dt][1] * il0);
        o1[0] = to_tf32(accO[dt][2] * il1); o1[1] = to_tf32(accO[dt][3] * il1);
    }
}

// ============================================================================
// Launch sequence
// ============================================================================
extern "C" void kernel_launch(void* const* d_in, const int* in_sizes, int n_in,
                              void* d_out, int out_size) {
    const float* tokens = (const float*)d_in[0];
    const float* xy     = (const float*)d_in[1];
    const float* Wq     = (const float*)d_in[2];
    const float* Wk     = (const float*)d_in[3];
    const float* Wv     = (const float*)d_in[4];
    const float* Wo     = (const float*)d_in[5];
    const float* bo     = (const float*)d_in[6];
    const float* W1     = (const float*)d_in[7];
    const float* b1     = (const float*)d_in[8];
    const float* W2     = (const float*)d_in[9];
    const float* b2     = (const float*)d_in[10];
    const float* g1     = (const float*)d_in[11];
    const float* be1    = (const float*)d_in[12];
    const float* g2     = (const float*)d_in[13];
    const float* be2    = (const float*)d_in[14];
    const float* gf     = (const float*)d_in[15];
    const float* bf     = (const float*)d_in[16];
    const int*   alive  = (const int*)d_in[17];
    const int*   species= (const int*)d_in[18];
    float* out = (float*)d_out;

    constexpr int GS128 = 3 * (BM * AST + BK * 136) * 4;       // 56832
    constexpr int GS64  = 3 * (64 * AST + BK * 136) * 4;       // 41472
    constexpr int FLASH_SMEM = (128 * 68 + 64 * 72 * 4) * 4 + 2 * 64 * 16; // 110592

    cudaFuncSetAttribute(gemm3<0>, cudaFuncAttributeMaxDynamicSharedMemorySize, GS128);
    cudaFuncSetAttribute(gemm3<2>, cudaFuncAttributeMaxDynamicSharedMemorySize, GS128);
    cudaFuncSetAttribute(gemm64,   cudaFuncAttributeMaxDynamicSharedMemorySize, GS64);
    cudaFuncSetAttribute(flash_attn, cudaFuncAttributeMaxDynamicSharedMemorySize, FLASH_SMEM);

    // weight rounding: one launch
    {
        const int n4b = Lv * Dv * DFFv / 4;        // 1572864
        round_w_all<<<dim3((n4b + 255) / 256, 6), 256>>>(
            (const float4*)Wq, (const float4*)Wk, (const float4*)Wv,
            (const float4*)Wo, (const float4*)W1, (const float4*)W2);
    }
    kattr_build<<<ROWS / 256, 256>>>(xy, alive, species);
    copy_tokens<<<(ROWS * Dv / 4) / 256, 256>>>((const float4*)tokens);

    for (int l = 0; l < Lv; l++) {
        const size_t oD = (size_t)l * Dv * Dv;
        const size_t oF = (size_t)l * Dv * DFFv;
        // ln1: x -> h (rounded)
        ln_kernel<<<ROWS / 8, 256>>>(6, 0, nullptr, g1 + l * Dv, be1 + l * Dv, 1);
        // fused QKV (q scaled+rounded, k transposed+rounded, v rounded)
        gemm3<0><<<dim3(Dv / 128, ROWS / 128, 3), 256, GS128>>>(
            0, 0, oD, 3, Dv, Dv, nullptr);
        // flash attention -> o (rounded)
        flash_attn<<<dim3(Nv / 128, Bv * 8), 256, FLASH_SMEM>>>();
        // x += o Wo + bo
        gemm64<<<dim3(Dv / 128, ROWS / 64), 256, GS64>>>(1, 3, oD, Dv, Dv, bo + l * Dv);
        // ln2: x -> h (rounded)
        ln_kernel<<<ROWS / 8, 256>>>(6, 0, nullptr, g2 + l * Dv, be2 + l * Dv, 1);
        // ff = gelu(h W1 + b1) (rounded)
        gemm3<2><<<dim3(DFFv / 128, ROWS / 128, 1), 256, GS128>>>(
            0, 4, oF, 2, DFFv, Dv, b1 + l * DFFv);
        // x += ff W2 + b2
        gemm64<<<dim3(Dv / 128, ROWS / 64), 256, GS64>>>(2, 5, oF, Dv, DFFv, b2 + l * Dv);
    }

    // final layernorm -> out (full fp32)
    ln_kernel<<<ROWS / 8, 256>>>(6, 1, out, gf, bf, 0);
}